// round 4
// baseline (speedup 1.0000x reference)
#include <cuda_runtime.h>

typedef unsigned long long ull;

#define GSZ 32
#define ATS 36   // aT row stride (floats): 16B-aligned, conflict-free f4 reads
#define UTS 33   // uT row stride (floats): conflict-free scalar access

// smem layout (floats): aT[512*36] | uT[512*33] | W2s[512*32] | hs[32*68] | red[512] | bn2[64]
#define OFF_AT   0
#define OFF_UT   (512*ATS)
#define OFF_W2   (OFF_UT + 512*UTS)
#define OFF_HS   (OFF_W2 + 512*32)
#define OFF_RED  (OFF_HS + 32*68)
#define OFF_BN2  (OFF_RED + 512)
#define SMEM_FLOATS (OFF_BN2 + 64)
#define SMEM_BYTES  (SMEM_FLOATS * 4)

__device__ float g_M0[512];
__device__ float g_M1[512];
__device__ float g_cv[512];

__device__ __forceinline__ ull pack2(float lo, float hi) {
    ull r; asm("mov.b64 %0, {%1,%2};" : "=l"(r) : "f"(lo), "f"(hi)); return r;
}
__device__ __forceinline__ void unpack2(ull v, float& lo, float& hi) {
    asm("mov.b64 {%0,%1}, %2;" : "=f"(lo), "=f"(hi) : "l"(v));
}
__device__ __forceinline__ ull ffma2(ull a, ull b, ull c) {
    ull d; asm("fma.rn.f32x2 %0, %1, %2, %3;" : "=l"(d) : "l"(a), "l"(b), "l"(c)); return d;
}
__device__ __forceinline__ ull fadd2(ull a, ull b) {
    ull d; asm("add.rn.f32x2 %0, %1, %2;" : "=l"(d) : "l"(a), "l"(b)); return d;
}

// Fold W_spatial through W1's top half:  M = Wsp @ W1[:64],  cv = bsp @ W1[:64] + b1
__global__ void prep_kernel(const float* __restrict__ Wsp, const float* __restrict__ bsp,
                            const float* __restrict__ W1, const float* __restrict__ b1) {
    int k = threadIdx.x;  // 512 threads
    float m0 = 0.f, m1 = 0.f, cc = 0.f;
#pragma unroll 8
    for (int e = 0; e < 64; e++) {
        float w = W1[e * 512 + k];
        m0 += Wsp[e] * w;
        m1 += Wsp[64 + e] * w;
        cc += bsp[e] * w;
    }
    g_M0[k] = m0; g_M1[k] = m1; g_cv[k] = cc + b1[k];
}

__global__ void __launch_bounds__(256, 1)
pool_kernel(const float* __restrict__ h_states, const float* __restrict__ end_pos,
            const float* __restrict__ W1,
            const float* __restrict__ gamma1, const float* __restrict__ beta1,
            const float* __restrict__ W2, const float* __restrict__ b2,
            const float* __restrict__ gamma2, const float* __restrict__ beta2,
            float* __restrict__ out) {
    extern __shared__ float sm[];
    float* aT  = sm + OFF_AT;
    float* uT  = sm + OFF_UT;
    float* W2s = sm + OFF_W2;
    float* hs  = sm + OFF_HS;
    float* red = sm + OFF_RED;
    float* bn2 = sm + OFF_BN2;

    const int n    = blockIdx.x;
    const int tid  = threadIdx.x;
    const int j    = tid >> 3;     // 0..31 (also plays role of i in phase 3)
    const int jb   = tid & 7;      // 0..7  (j-block / k-chunk selector)
    const int base = n * GSZ;

    // ---- cooperative loads: W2 -> smem, h rows -> smem (padded stride 68) ----
    {
        const float4* src = (const float4*)W2;
        float4* dst = (float4*)W2s;
        for (int idx = tid; idx < 512 * 32 / 4; idx += 256) dst[idx] = src[idx];
        for (int idx = tid; idx < 32 * 64; idx += 256) {
            int jr = idx >> 6, t = idx & 63;
            hs[jr * 68 + t] = h_states[(size_t)(base + jr) * 64 + t];
        }
    }
    __syncthreads();

    // ---- phase 1: a_j[k] = hW[j,k] + u_j[k] + cv[k];  u stored separately ----
    const float2 p = ((const float2*)end_pos)[base + j];
    const float px = p.x, py = p.y;
    const float* hrow = hs + j * 68;

#pragma unroll 1
    for (int kc = 0; kc < 4; kc++) {
        const int k0 = jb * 64 + kc * 16;
        ull acc[8];
#pragma unroll
        for (int q = 0; q < 8; q++) acc[q] = 0ull;
        const float* wb = W1 + 64 * 512 + k0;
#pragma unroll 8
        for (int t = 0; t < 64; t++) {
            float hv = hrow[t];
            ull hh = pack2(hv, hv);
            const ulonglong2* wp = (const ulonglong2*)(wb + (size_t)t * 512);
            ulonglong2 wa = wp[0], wbv = wp[1], wc = wp[2], wd = wp[3];
            acc[0] = ffma2(hh, wa.x,  acc[0]); acc[1] = ffma2(hh, wa.y,  acc[1]);
            acc[2] = ffma2(hh, wbv.x, acc[2]); acc[3] = ffma2(hh, wbv.y, acc[3]);
            acc[4] = ffma2(hh, wc.x,  acc[4]); acc[5] = ffma2(hh, wc.y,  acc[5]);
            acc[6] = ffma2(hh, wd.x,  acc[6]); acc[7] = ffma2(hh, wd.y,  acc[7]);
        }
#pragma unroll
        for (int q = 0; q < 8; q++) {
            int k = k0 + 2 * q;
            float lo, hi; unpack2(acc[q], lo, hi);
            float2 m0 = *(const float2*)(g_M0 + k);
            float2 m1 = *(const float2*)(g_M1 + k);
            float2 cv = *(const float2*)(g_cv + k);
            float u0 = px * m0.x + py * m1.x;
            float u1 = px * m0.y + py * m1.y;
            aT[(k    ) * ATS + j] = lo + u0 + cv.x;
            aT[(k + 1) * ATS + j] = hi + u1 + cv.y;
            uT[(k    ) * UTS + j] = u0;
            uT[(k + 1) * UTS + j] = u1;
        }
    }
    __syncthreads();

    // ---- phase 2: BN1 via factored statistics; fold scale/shift in place ----
    for (int k = tid; k < 512; k += 256) {
        float sa = 0.f, sa2 = 0.f, su = 0.f, su2 = 0.f;
#pragma unroll 8
        for (int jj = 0; jj < 32; jj++) {
            float a = aT[k * ATS + jj]; sa += a; sa2 += a * a;
            float u = uT[k * UTS + jj]; su += u; su2 += u * u;
        }
        const float inv = 1.0f / 32.0f;
        float ma = sa * inv, mu = su * inv;
        float var  = (sa2 * inv - ma * ma) + (su2 * inv - mu * mu);
        float mean = ma - mu;
        float al = gamma1[k] * rsqrtf(var + 1e-5f);
        float bp = beta1[k] - al * mean;
#pragma unroll 8
        for (int jj = 0; jj < 32; jj++) {
            aT[k * ATS + jj] = al * aT[k * ATS + jj] + bp;   // a-tilde
            uT[k * UTS + jj] = al * uT[k * UTS + jj];        // u-tilde
        }
    }
    __syncthreads();

    // ---- phase 3: layer-2 GEMM.  relu(aT'[k][j] - uT'[k][i]) @ W2  (f32x2) ----
    // thread = (i = tid>>3, jb = tid&7): rows j = jb*4..jb*4+3, all 32 columns.
    const int i = j;
    ull acc[4][16];
    {
        const ull* b2u = (const ull*)b2;
#pragma unroll
        for (int c2 = 0; c2 < 16; c2++) {
            ull b = b2u[c2];
            acc[0][c2] = b; acc[1][c2] = b; acc[2][c2] = b; acc[3][c2] = b;
        }
    }
    const float4* aT4 = (const float4*)aT;  // row stride = 9 float4
#pragma unroll 2
    for (int k = 0; k < 512; k++) {
        float u = uT[k * UTS + i];
        float4 av = aT4[k * 9 + jb];
        float x0 = fmaxf(av.x - u, 0.f);
        float x1 = fmaxf(av.y - u, 0.f);
        float x2 = fmaxf(av.z - u, 0.f);
        float x3 = fmaxf(av.w - u, 0.f);
        ull X0 = pack2(x0, x0), X1 = pack2(x1, x1), X2 = pack2(x2, x2), X3 = pack2(x3, x3);
        const ulonglong2* wrow = (const ulonglong2*)(W2s + k * 32);
#pragma unroll
        for (int c4 = 0; c4 < 8; c4++) {
            ulonglong2 w = wrow[c4];  // columns 4*c4 .. 4*c4+3 (broadcast load)
            int c2 = c4 * 2;
            acc[0][c2]     = ffma2(X0, w.x, acc[0][c2]);
            acc[1][c2]     = ffma2(X1, w.x, acc[1][c2]);
            acc[2][c2]     = ffma2(X2, w.x, acc[2][c2]);
            acc[3][c2]     = ffma2(X3, w.x, acc[3][c2]);
            acc[0][c2 + 1] = ffma2(X0, w.y, acc[0][c2 + 1]);
            acc[1][c2 + 1] = ffma2(X1, w.y, acc[1][c2 + 1]);
            acc[2][c2 + 1] = ffma2(X2, w.y, acc[2][c2 + 1]);
            acc[3][c2 + 1] = ffma2(X3, w.y, acc[3][c2 + 1]);
        }
    }

    // ---- BN2 statistics: packed per-thread partials -> warp shuffle -> smem ----
    ull ps2[16], pq2[16];
#pragma unroll
    for (int c2 = 0; c2 < 16; c2++) { ps2[c2] = 0ull; pq2[c2] = 0ull; }
#pragma unroll
    for (int jj = 0; jj < 4; jj++)
#pragma unroll
        for (int c2 = 0; c2 < 16; c2++) {
            ull v = acc[jj][c2];
            ps2[c2] = fadd2(ps2[c2], v);
            pq2[c2] = ffma2(v, v, pq2[c2]);
        }
#pragma unroll
    for (int c2 = 0; c2 < 16; c2++) {
#pragma unroll
        for (int d = 16; d > 0; d >>= 1) {
            ps2[c2] = fadd2(ps2[c2], __shfl_xor_sync(0xffffffffu, ps2[c2], d));
            pq2[c2] = fadd2(pq2[c2], __shfl_xor_sync(0xffffffffu, pq2[c2], d));
        }
    }
    {
        const int lane = tid & 31, w = tid >> 5;
        ull* red_u = (ull*)red;
        if (lane == 0) {
#pragma unroll
            for (int c2 = 0; c2 < 16; c2++) {
                red_u[w * 32 + c2]      = ps2[c2];
                red_u[w * 32 + 16 + c2] = pq2[c2];
            }
        }
    }
    __syncthreads();
    if (tid < 32) {
        const ull* red_u = (const ull*)red;
        int c = tid, c2 = c >> 1; bool hi = c & 1;
        float S = 0.f, S2 = 0.f;
#pragma unroll
        for (int w2 = 0; w2 < 8; w2++) {
            float lo, h2;
            unpack2(red_u[w2 * 32 + c2], lo, h2);      S  += hi ? h2 : lo;
            unpack2(red_u[w2 * 32 + 16 + c2], lo, h2); S2 += hi ? h2 : lo;
        }
        float mean = S * (1.0f / 1024.0f);
        float var  = S2 * (1.0f / 1024.0f) - mean * mean;
        float al = gamma2[c] * rsqrtf(var + 1e-5f);
        bn2[c] = al;
        bn2[32 + c] = beta2[c] - al * mean;
    }
    __syncthreads();

    // ---- BN2 apply + relu + max over j (relu commutes with max; init 0) ----
    float mx[32];
#pragma unroll
    for (int c2 = 0; c2 < 16; c2++) {
        float a0 = bn2[2 * c2], a1 = bn2[2 * c2 + 1];
        float b0 = bn2[32 + 2 * c2], b1v = bn2[33 + 2 * c2];
        float m0 = 0.f, m1 = 0.f;
#pragma unroll
        for (int jj = 0; jj < 4; jj++) {
            float y0, y1; unpack2(acc[jj][c2], y0, y1);
            m0 = fmaxf(m0, a0 * y0 + b0);
            m1 = fmaxf(m1, a1 * y1 + b1v);
        }
        mx[2 * c2] = m0; mx[2 * c2 + 1] = m1;
    }
#pragma unroll
    for (int c = 0; c < 32; c++) {
#pragma unroll
        for (int d = 1; d < 8; d <<= 1)
            mx[c] = fmaxf(mx[c], __shfl_xor_sync(0xffffffffu, mx[c], d));
    }
    if (jb == 0) {
        float4* op = (float4*)(out + (size_t)(base + i) * 32);
        op[0] = make_float4(mx[0],  mx[1],  mx[2],  mx[3]);
        op[1] = make_float4(mx[4],  mx[5],  mx[6],  mx[7]);
        op[2] = make_float4(mx[8],  mx[9],  mx[10], mx[11]);
        op[3] = make_float4(mx[12], mx[13], mx[14], mx[15]);
        op[4] = make_float4(mx[16], mx[17], mx[18], mx[19]);
        op[5] = make_float4(mx[20], mx[21], mx[22], mx[23]);
        op[6] = make_float4(mx[24], mx[25], mx[26], mx[27]);
        op[7] = make_float4(mx[28], mx[29], mx[30], mx[31]);
    }
}

extern "C" void kernel_launch(void* const* d_in, const int* in_sizes, int n_in,
                              void* d_out, int out_size) {
    const float* h_states = (const float*)d_in[0];
    // d_in[1] = seq_start_end (uniform groups of 32; structure is implied by shapes)
    const float* end_pos  = (const float*)d_in[2];
    const float* Wsp      = (const float*)d_in[3];
    const float* bsp      = (const float*)d_in[4];
    const float* W1       = (const float*)d_in[5];
    const float* b1       = (const float*)d_in[6];
    const float* gamma1   = (const float*)d_in[7];
    const float* beta1    = (const float*)d_in[8];
    const float* W2       = (const float*)d_in[9];
    const float* b2       = (const float*)d_in[10];
    const float* gamma2   = (const float*)d_in[11];
    const float* beta2    = (const float*)d_in[12];
    float* out = (float*)d_out;

    cudaFuncSetAttribute(pool_kernel, cudaFuncAttributeMaxDynamicSharedMemorySize, SMEM_BYTES);

    prep_kernel<<<1, 512>>>(Wsp, bsp, W1, b1);
    pool_kernel<<<256, 256, SMEM_BYTES>>>(h_states, end_pos, W1, gamma1, beta1,
                                          W2, b2, gamma2, beta2, out);
}

// round 5
// speedup vs baseline: 1.4546x; 1.4546x over previous
#include <cuda_runtime.h>

typedef unsigned long long ull;

#define GSZ 32
#define ATS 36   // aT row stride (floats): 16B-aligned, conflict-free vector reads
#define AT2S 18  // aT row stride in float2
#define UTS 33   // uT row stride (floats): conflict-free scalar access

// smem layout (floats): aT[512*36] | uT[512*33] | W2s[512*32] | hs[32*68] | red[1024] | bn2[64]
#define OFF_AT   0
#define OFF_UT   (512*ATS)
#define OFF_W2   (OFF_UT + 512*UTS)
#define OFF_HS   (OFF_W2 + 512*32)
#define OFF_RED  (OFF_HS + 32*68)
#define OFF_BN2  (OFF_RED + 1024)
#define SMEM_FLOATS (OFF_BN2 + 64)
#define SMEM_BYTES  (SMEM_FLOATS * 4)

__device__ float g_M0[512];
__device__ float g_M1[512];
__device__ float g_cv[512];

__device__ __forceinline__ ull pack2(float lo, float hi) {
    ull r; asm("mov.b64 %0, {%1,%2};" : "=l"(r) : "f"(lo), "f"(hi)); return r;
}
__device__ __forceinline__ void unpack2(ull v, float& lo, float& hi) {
    asm("mov.b64 {%0,%1}, %2;" : "=f"(lo), "=f"(hi) : "l"(v));
}
__device__ __forceinline__ ull ffma2(ull a, ull b, ull c) {
    ull d; asm("fma.rn.f32x2 %0, %1, %2, %3;" : "=l"(d) : "l"(a), "l"(b), "l"(c)); return d;
}
__device__ __forceinline__ ull fadd2(ull a, ull b) {
    ull d; asm("add.rn.f32x2 %0, %1, %2;" : "=l"(d) : "l"(a), "l"(b)); return d;
}

// Fold W_spatial through W1's top half:  M = Wsp @ W1[:64],  cv = bsp @ W1[:64] + b1
__global__ void prep_kernel(const float* __restrict__ Wsp, const float* __restrict__ bsp,
                            const float* __restrict__ W1, const float* __restrict__ b1) {
    int k = threadIdx.x;  // 512 threads
    float m0 = 0.f, m1 = 0.f, cc = 0.f;
#pragma unroll 8
    for (int e = 0; e < 64; e++) {
        float w = W1[e * 512 + k];
        m0 += Wsp[e] * w;
        m1 += Wsp[64 + e] * w;
        cc += bsp[e] * w;
    }
    g_M0[k] = m0; g_M1[k] = m1; g_cv[k] = cc + b1[k];
}

__global__ void __launch_bounds__(512, 1)
pool_kernel(const float* __restrict__ h_states, const float* __restrict__ end_pos,
            const float* __restrict__ W1,
            const float* __restrict__ gamma1, const float* __restrict__ beta1,
            const float* __restrict__ W2, const float* __restrict__ b2,
            const float* __restrict__ gamma2, const float* __restrict__ beta2,
            float* __restrict__ out) {
    extern __shared__ float sm[];
    float* aT  = sm + OFF_AT;
    float* uT  = sm + OFF_UT;
    float* W2s = sm + OFF_W2;
    float* hs  = sm + OFF_HS;
    float* red = sm + OFF_RED;
    float* bn2 = sm + OFF_BN2;

    const int n    = blockIdx.x;
    const int tid  = threadIdx.x;
    const int base = n * GSZ;

    // ---- cooperative loads: W2 -> smem, h rows -> smem (padded stride 68) ----
    {
        const float4* src = (const float4*)W2;
        float4* dst = (float4*)W2s;
        for (int idx = tid; idx < 512 * 32 / 4; idx += 512) dst[idx] = src[idx];
        for (int idx = tid; idx < 32 * 64; idx += 512) {
            int jr = idx >> 6, t = idx & 63;
            hs[jr * 68 + t] = h_states[(size_t)(base + jr) * 64 + t];
        }
    }
    __syncthreads();

    // ---- phase 1: a_j[k] = hW[j,k] + u_j[k] + cv[k];  u stored separately ----
    // thread = (j = tid>>4, q = tid&15): 32 k-values (q*32 .. q*32+31) for ped j
    {
        const int j  = tid >> 4;
        const int q  = tid & 15;
        const int k0 = q * 32;
        const float2 p = ((const float2*)end_pos)[base + j];
        const float px = p.x, py = p.y;
        const float* hrow = hs + j * 68;

        ull acc[16];
#pragma unroll
        for (int t = 0; t < 16; t++) acc[t] = 0ull;
        const float* wb = W1 + 64 * 512 + k0;
#pragma unroll 4
        for (int t = 0; t < 64; t++) {
            float hv = hrow[t];
            ull hh = pack2(hv, hv);
            const ulonglong2* wp = (const ulonglong2*)(wb + (size_t)t * 512);
            ulonglong2 wa = wp[0], wbv = wp[1], wc = wp[2], wd = wp[3];
            acc[0]  = ffma2(hh, wa.x,  acc[0]);  acc[1]  = ffma2(hh, wa.y,  acc[1]);
            acc[2]  = ffma2(hh, wbv.x, acc[2]);  acc[3]  = ffma2(hh, wbv.y, acc[3]);
            acc[4]  = ffma2(hh, wc.x,  acc[4]);  acc[5]  = ffma2(hh, wc.y,  acc[5]);
            acc[6]  = ffma2(hh, wd.x,  acc[6]);  acc[7]  = ffma2(hh, wd.y,  acc[7]);
            wp += 4;
            ulonglong2 we = wp[0], wf = wp[1], wg = wp[2], wh = wp[3];
            acc[8]  = ffma2(hh, we.x,  acc[8]);  acc[9]  = ffma2(hh, we.y,  acc[9]);
            acc[10] = ffma2(hh, wf.x,  acc[10]); acc[11] = ffma2(hh, wf.y,  acc[11]);
            acc[12] = ffma2(hh, wg.x,  acc[12]); acc[13] = ffma2(hh, wg.y,  acc[13]);
            acc[14] = ffma2(hh, wh.x,  acc[14]); acc[15] = ffma2(hh, wh.y,  acc[15]);
        }
#pragma unroll
        for (int qq = 0; qq < 16; qq++) {
            int k = k0 + 2 * qq;
            float lo, hi; unpack2(acc[qq], lo, hi);
            float2 m0 = *(const float2*)(g_M0 + k);
            float2 m1 = *(const float2*)(g_M1 + k);
            float2 cv = *(const float2*)(g_cv + k);
            float u0 = px * m0.x + py * m1.x;
            float u1 = px * m0.y + py * m1.y;
            aT[(k    ) * ATS + j] = lo + u0 + cv.x;
            aT[(k + 1) * ATS + j] = hi + u1 + cv.y;
            uT[(k    ) * UTS + j] = u0;
            uT[(k + 1) * UTS + j] = u1;
        }
    }
    __syncthreads();

    // ---- phase 2: BN1 via factored statistics; fold scale/shift in place ----
    {
        const int k = tid;  // 512 threads cover 512 features exactly
        float sa = 0.f, sa2 = 0.f, su = 0.f, su2 = 0.f;
#pragma unroll 8
        for (int jj = 0; jj < 32; jj++) {
            float a = aT[k * ATS + jj]; sa += a; sa2 += a * a;
            float u = uT[k * UTS + jj]; su += u; su2 += u * u;
        }
        const float inv = 1.0f / 32.0f;
        float ma = sa * inv, mu = su * inv;
        float var  = (sa2 * inv - ma * ma) + (su2 * inv - mu * mu);
        float mean = ma - mu;
        float al = gamma1[k] * rsqrtf(var + 1e-5f);
        float bp = beta1[k] - al * mean;
#pragma unroll 8
        for (int jj = 0; jj < 32; jj++) {
            aT[k * ATS + jj] = al * aT[k * ATS + jj] + bp;   // a-tilde
            uT[k * UTS + jj] = al * uT[k * UTS + jj];        // u-tilde
        }
    }
    __syncthreads();

    // ---- phase 3: layer-2 GEMM.  relu(aT'[k][j] - uT'[k][i]) @ W2  (f32x2) ----
    // thread = (i = tid>>4, jh = tid&15): rows j = jh*2, jh*2+1, all 32 columns.
    const int i  = tid >> 4;
    const int jh = tid & 15;
    ull acc[2][16];
    {
        const ull* b2u = (const ull*)b2;
#pragma unroll
        for (int c2 = 0; c2 < 16; c2++) {
            ull b = b2u[c2];
            acc[0][c2] = b; acc[1][c2] = b;
        }
    }
    {
        const float*  up = uT + i;
        const float2* a2 = (const float2*)aT + jh;
        const ulonglong2* wr = (const ulonglong2*)W2s;
#pragma unroll 2
        for (int k = 0; k < 512; k++) {
            float u  = up[k * UTS];
            float2 av = a2[k * AT2S];
            float x0 = fmaxf(av.x - u, 0.f);
            float x1 = fmaxf(av.y - u, 0.f);
            ull X0 = pack2(x0, x0), X1 = pack2(x1, x1);
            const ulonglong2* wrow = wr + k * 8;
#pragma unroll
            for (int c4 = 0; c4 < 8; c4++) {
                ulonglong2 w = wrow[c4];  // broadcast load (uniform per warp)
                int c2 = c4 * 2;
                acc[0][c2]     = ffma2(X0, w.x, acc[0][c2]);
                acc[1][c2]     = ffma2(X1, w.x, acc[1][c2]);
                acc[0][c2 + 1] = ffma2(X0, w.y, acc[0][c2 + 1]);
                acc[1][c2 + 1] = ffma2(X1, w.y, acc[1][c2 + 1]);
            }
        }
    }

    // ---- BN2 statistics: transient per-c2 shuffle reductions (no persistent regs) ----
    {
        const int lane = tid & 31, w = tid >> 5;
        ull* red_u = (ull*)red;
#pragma unroll
        for (int c2 = 0; c2 < 16; c2++) {
            ull v0 = acc[0][c2], v1 = acc[1][c2];
            ull s = fadd2(v0, v1);
            ull qv = ffma2(v0, v0, ffma2(v1, v1, 0ull));
#pragma unroll
            for (int d = 16; d > 0; d >>= 1) {
                s  = fadd2(s,  __shfl_xor_sync(0xffffffffu, s,  d));
                qv = fadd2(qv, __shfl_xor_sync(0xffffffffu, qv, d));
            }
            if (lane == 0) {
                red_u[w * 32 + c2]      = s;
                red_u[w * 32 + 16 + c2] = qv;
            }
        }
    }
    __syncthreads();
    if (tid < 32) {
        const ull* red_u = (const ull*)red;
        int c = tid, c2 = c >> 1; bool hi = c & 1;
        float S = 0.f, S2 = 0.f;
#pragma unroll
        for (int w2 = 0; w2 < 16; w2++) {
            float lo, h2;
            unpack2(red_u[w2 * 32 + c2], lo, h2);      S  += hi ? h2 : lo;
            unpack2(red_u[w2 * 32 + 16 + c2], lo, h2); S2 += hi ? h2 : lo;
        }
        float mean = S * (1.0f / 1024.0f);
        float var  = S2 * (1.0f / 1024.0f) - mean * mean;
        float al = gamma2[c] * rsqrtf(var + 1e-5f);
        bn2[c] = al;
        bn2[32 + c] = beta2[c] - al * mean;
    }
    __syncthreads();

    // ---- BN2 apply + relu + max over j (relu commutes with max; init 0) ----
    float mx[32];
#pragma unroll
    for (int c2 = 0; c2 < 16; c2++) {
        float a0 = bn2[2 * c2], a1 = bn2[2 * c2 + 1];
        float b0 = bn2[32 + 2 * c2], b1v = bn2[33 + 2 * c2];
        float m0 = 0.f, m1 = 0.f;
#pragma unroll
        for (int jj = 0; jj < 2; jj++) {
            float y0, y1; unpack2(acc[jj][c2], y0, y1);
            m0 = fmaxf(m0, a0 * y0 + b0);
            m1 = fmaxf(m1, a1 * y1 + b1v);
        }
        mx[2 * c2] = m0; mx[2 * c2 + 1] = m1;
    }
#pragma unroll
    for (int c = 0; c < 32; c++) {
#pragma unroll
        for (int d = 1; d < 16; d <<= 1)   // butterfly over the 16 jh lanes
            mx[c] = fmaxf(mx[c], __shfl_xor_sync(0xffffffffu, mx[c], d));
    }
    if (jh == 0) {
        float4* op = (float4*)(out + (size_t)(base + i) * 32);
        op[0] = make_float4(mx[0],  mx[1],  mx[2],  mx[3]);
        op[1] = make_float4(mx[4],  mx[5],  mx[6],  mx[7]);
        op[2] = make_float4(mx[8],  mx[9],  mx[10], mx[11]);
        op[3] = make_float4(mx[12], mx[13], mx[14], mx[15]);
        op[4] = make_float4(mx[16], mx[17], mx[18], mx[19]);
        op[5] = make_float4(mx[20], mx[21], mx[22], mx[23]);
        op[6] = make_float4(mx[24], mx[25], mx[26], mx[27]);
        op[7] = make_float4(mx[28], mx[29], mx[30], mx[31]);
    }
}

extern "C" void kernel_launch(void* const* d_in, const int* in_sizes, int n_in,
                              void* d_out, int out_size) {
    const float* h_states = (const float*)d_in[0];
    // d_in[1] = seq_start_end (uniform groups of 32; structure implied by shapes)
    const float* end_pos  = (const float*)d_in[2];
    const float* Wsp      = (const float*)d_in[3];
    const float* bsp      = (const float*)d_in[4];
    const float* W1       = (const float*)d_in[5];
    const float* b1       = (const float*)d_in[6];
    const float* gamma1   = (const float*)d_in[7];
    const float* beta1    = (const float*)d_in[8];
    const float* W2       = (const float*)d_in[9];
    const float* b2       = (const float*)d_in[10];
    const float* gamma2   = (const float*)d_in[11];
    const float* beta2    = (const float*)d_in[12];
    float* out = (float*)d_out;

    cudaFuncSetAttribute(pool_kernel, cudaFuncAttributeMaxDynamicSharedMemorySize, SMEM_BYTES);

    prep_kernel<<<1, 512>>>(Wsp, bsp, W1, b1);
    pool_kernel<<<256, 512, SMEM_BYTES>>>(h_states, end_pos, W1, gamma1, beta1,
                                          W2, b2, gamma2, beta2, out);
}

// round 6
// speedup vs baseline: 1.8804x; 1.2927x over previous
#include <cuda_runtime.h>

typedef unsigned long long ull;

#define GSZ 32
#define ATS 36   // aT row stride (floats): float4-aligned rows, XOR-swizzled blocks
#define AT4S 9   // aT row stride in float4
#define UTS 33   // uT row stride (floats)

// smem layout (floats): aT[512*36] | uT[512*33] | W2s[512*32] | hs[32*68] | red[2048] | bn2[64]
#define OFF_AT   0
#define OFF_UT   (512*ATS)
#define OFF_W2   (OFF_UT + 512*UTS)
#define OFF_HS   (OFF_W2 + 512*32)
#define OFF_RED  (OFF_HS + 32*68)
#define OFF_BN2  (OFF_RED + 2048)
#define SMEM_FLOATS (OFF_BN2 + 64)
#define SMEM_BYTES  (SMEM_FLOATS * 4)

__device__ float g_M0[512];
__device__ float g_M1[512];
__device__ float g_cv[512];

__device__ __forceinline__ ull pack2(float lo, float hi) {
    ull r; asm("mov.b64 %0, {%1,%2};" : "=l"(r) : "f"(lo), "f"(hi)); return r;
}
__device__ __forceinline__ void unpack2(ull v, float& lo, float& hi) {
    asm("mov.b64 {%0,%1}, %2;" : "=f"(lo), "=f"(hi) : "l"(v));
}
__device__ __forceinline__ ull ffma2(ull a, ull b, ull c) {
    ull d; asm("fma.rn.f32x2 %0, %1, %2, %3;" : "=l"(d) : "l"(a), "l"(b), "l"(c)); return d;
}
__device__ __forceinline__ ull fadd2(ull a, ull b) {
    ull d; asm("add.rn.f32x2 %0, %1, %2;" : "=l"(d) : "l"(a), "l"(b)); return d;
}

// Fold W_spatial through W1's top half:  M = Wsp @ W1[:64],  cv = bsp @ W1[:64] + b1
__global__ void prep_kernel(const float* __restrict__ Wsp, const float* __restrict__ bsp,
                            const float* __restrict__ W1, const float* __restrict__ b1) {
    int k = threadIdx.x;  // 512 threads
    float m0 = 0.f, m1 = 0.f, cc = 0.f;
#pragma unroll 8
    for (int e = 0; e < 64; e++) {
        float w = W1[e * 512 + k];
        m0 += Wsp[e] * w;
        m1 += Wsp[64 + e] * w;
        cc += bsp[e] * w;
    }
    g_M0[k] = m0; g_M1[k] = m1; g_cv[k] = cc + b1[k];
}

__global__ void __launch_bounds__(1024, 1)
pool_kernel(const float* __restrict__ h_states, const float* __restrict__ end_pos,
            const float* __restrict__ W1,
            const float* __restrict__ gamma1, const float* __restrict__ beta1,
            const float* __restrict__ W2, const float* __restrict__ b2,
            const float* __restrict__ gamma2, const float* __restrict__ beta2,
            float* __restrict__ out) {
    extern __shared__ float sm[];
    float* aT  = sm + OFF_AT;
    float* uT  = sm + OFF_UT;
    float* W2s = sm + OFF_W2;
    float* hs  = sm + OFF_HS;
    float* red = sm + OFF_RED;
    float* bn2 = sm + OFF_BN2;

    const int n    = blockIdx.x;
    const int tid  = threadIdx.x;
    const int base = n * GSZ;

    // ---- cooperative loads: W2 -> smem, h rows -> smem (padded stride 68) ----
    {
        const float4* src = (const float4*)W2;
        float4* dst = (float4*)W2s;
        for (int idx = tid; idx < 512 * 32 / 4; idx += 1024) dst[idx] = src[idx];
        for (int idx = tid; idx < 32 * 64; idx += 1024) {
            int jr = idx >> 6, t = idx & 63;
            hs[jr * 68 + t] = h_states[(size_t)(base + jr) * 64 + t];
        }
    }
    __syncthreads();

    // ---- phase 1: a_j[k] = hW[j,k] + u_j[k] + cv[k];  u stored separately ----
    // thread = (j = tid>>5, q = tid&31): 16 k-values (q*16 .. q*16+15) for ped j
    {
        const int j  = tid >> 5;
        const int q  = tid & 31;
        const int k0 = q * 16;
        const float2 p = ((const float2*)end_pos)[base + j];
        const float px = p.x, py = p.y;
        const float* hrow = hs + j * 68;

        ull acc[8];
#pragma unroll
        for (int t = 0; t < 8; t++) acc[t] = 0ull;
        const float* wb = W1 + 64 * 512 + k0;
#pragma unroll 2
        for (int t = 0; t < 64; t++) {
            float hv = hrow[t];
            ull hh = pack2(hv, hv);
            const ulonglong2* wp = (const ulonglong2*)(wb + (size_t)t * 512);
            ulonglong2 wa = wp[0], wbv = wp[1], wc = wp[2], wd = wp[3];
            acc[0] = ffma2(hh, wa.x,  acc[0]); acc[1] = ffma2(hh, wa.y,  acc[1]);
            acc[2] = ffma2(hh, wbv.x, acc[2]); acc[3] = ffma2(hh, wbv.y, acc[3]);
            acc[4] = ffma2(hh, wc.x,  acc[4]); acc[5] = ffma2(hh, wc.y,  acc[5]);
            acc[6] = ffma2(hh, wd.x,  acc[6]); acc[7] = ffma2(hh, wd.y,  acc[7]);
        }
#pragma unroll
        for (int qq = 0; qq < 8; qq++) {
            int k = k0 + 2 * qq;
            float lo, hi; unpack2(acc[qq], lo, hi);
            float2 m0 = *(const float2*)(g_M0 + k);
            float2 m1 = *(const float2*)(g_M1 + k);
            float2 cv = *(const float2*)(g_cv + k);
            float u0 = px * m0.x + py * m1.x;
            float u1 = px * m0.y + py * m1.y;
            // XOR swizzle: physical j' = j ^ (((k>>4)&7)<<2); k,k+1 share (k>>4)
            int jA = j ^ (((k >> 4) & 7) << 2);
            aT[(k    ) * ATS + jA] = lo + u0 + cv.x;
            aT[(k + 1) * ATS + jA] = hi + u1 + cv.y;
            uT[(k    ) * UTS + jA] = u0;
            uT[(k + 1) * UTS + jA] = u1;
        }
    }
    __syncthreads();

    // ---- phase 2: BN1 via factored statistics (order-free over swizzled j) ----
    // 2 threads per feature: thread handles 16 physical j's, combine via shfl.
    {
        const int k  = tid >> 1;
        const int jo = (tid & 1) * 16;
        float sa = 0.f, sa2 = 0.f, su = 0.f, su2 = 0.f;
#pragma unroll 4
        for (int jj = 0; jj < 16; jj++) {
            float a = aT[k * ATS + jo + jj]; sa += a; sa2 += a * a;
            float u = uT[k * UTS + jo + jj]; su += u; su2 += u * u;
        }
        sa  += __shfl_xor_sync(0xffffffffu, sa,  1);
        sa2 += __shfl_xor_sync(0xffffffffu, sa2, 1);
        su  += __shfl_xor_sync(0xffffffffu, su,  1);
        su2 += __shfl_xor_sync(0xffffffffu, su2, 1);
        const float inv = 1.0f / 32.0f;
        float ma = sa * inv, mu = su * inv;
        float var  = (sa2 * inv - ma * ma) + (su2 * inv - mu * mu);
        float mean = ma - mu;
        float al = gamma1[k] * rsqrtf(var + 1e-5f);
        float bp = beta1[k] - al * mean;
#pragma unroll 4
        for (int jj = 0; jj < 16; jj++) {
            aT[k * ATS + jo + jj] = al * aT[k * ATS + jo + jj] + bp;   // a-tilde
            uT[k * UTS + jo + jj] = al * uT[k * UTS + jo + jj];        // u-tilde
        }
    }
    __syncthreads();

    // ---- phase 3: layer-2 GEMM.  relu(aT'[k][j] - uT'[k][i]) @ W2  (f32x2) ----
    // thread = (i = tid>>5, j4 = (tid>>2)&7, ch = tid&3):
    //   rows j = j4*4..j4*4+3, cols ch*8..ch*8+7.  acc[4 rows][4 col-pairs].
    const int i  = tid >> 5;
    const int j4 = (tid >> 2) & 7;
    const int ch = tid & 3;
    ull acc2[4][4];
    {
        const ull* b2u = (const ull*)b2;
#pragma unroll
        for (int cp = 0; cp < 4; cp++) {
            ull b = b2u[ch * 4 + cp];
            acc2[0][cp] = b; acc2[1][cp] = b; acc2[2][cp] = b; acc2[3][cp] = b;
        }
    }
    {
        const float4* aT4 = (const float4*)aT;
        const ulonglong2* wr = (const ulonglong2*)W2s + ch * 2;
#pragma unroll 1
        for (int k = 0; k < 512; k++) {
            int s = (k >> 4) & 7;
            float  u  = uT[k * UTS + (i ^ (s << 2))];        // uniform per warp
            float4 av = aT4[k * AT4S + (j4 ^ s)];            // conflict-free perm
            float x0 = fmaxf(av.x - u, 0.f);
            float x1 = fmaxf(av.y - u, 0.f);
            float x2 = fmaxf(av.z - u, 0.f);
            float x3 = fmaxf(av.w - u, 0.f);
            ull X0 = pack2(x0, x0), X1 = pack2(x1, x1);
            ull X2 = pack2(x2, x2), X3 = pack2(x3, x3);
            const ulonglong2* wrow = wr + k * 8;
            ulonglong2 wA = wrow[0], wB = wrow[1];           // cols ch*8..ch*8+7
            acc2[0][0] = ffma2(X0, wA.x, acc2[0][0]);
            acc2[1][0] = ffma2(X1, wA.x, acc2[1][0]);
            acc2[2][0] = ffma2(X2, wA.x, acc2[2][0]);
            acc2[3][0] = ffma2(X3, wA.x, acc2[3][0]);
            acc2[0][1] = ffma2(X0, wA.y, acc2[0][1]);
            acc2[1][1] = ffma2(X1, wA.y, acc2[1][1]);
            acc2[2][1] = ffma2(X2, wA.y, acc2[2][1]);
            acc2[3][1] = ffma2(X3, wA.y, acc2[3][1]);
            acc2[0][2] = ffma2(X0, wB.x, acc2[0][2]);
            acc2[1][2] = ffma2(X1, wB.x, acc2[1][2]);
            acc2[2][2] = ffma2(X2, wB.x, acc2[2][2]);
            acc2[3][2] = ffma2(X3, wB.x, acc2[3][2]);
            acc2[0][3] = ffma2(X0, wB.y, acc2[0][3]);
            acc2[1][3] = ffma2(X1, wB.y, acc2[1][3]);
            acc2[2][3] = ffma2(X2, wB.y, acc2[2][3]);
            acc2[3][3] = ffma2(X3, wB.y, acc2[3][3]);
        }
    }

    // ---- BN2 statistics: reduce over in-thread j then over j4 lanes ----
    {
        ull* red_u = (ull*)red;
#pragma unroll
        for (int cp = 0; cp < 4; cp++) {
            ull v0 = acc2[0][cp], v1 = acc2[1][cp], v2 = acc2[2][cp], v3 = acc2[3][cp];
            ull s = fadd2(fadd2(v0, v1), fadd2(v2, v3));
            ull qv = ffma2(v0, v0, ffma2(v1, v1, ffma2(v2, v2, ffma2(v3, v3, 0ull))));
#pragma unroll
            for (int d = 4; d <= 16; d <<= 1) {
                s  = fadd2(s,  __shfl_xor_sync(0xffffffffu, s,  d));
                qv = fadd2(qv, __shfl_xor_sync(0xffffffffu, qv, d));
            }
            if (j4 == 0) {
                red_u[i * 32 + ch * 4 + cp]      = s;
                red_u[i * 32 + 16 + ch * 4 + cp] = qv;
            }
        }
    }
    __syncthreads();
    if (tid < 32) {
        const ull* red_u = (const ull*)red;
        int c = tid;
        int uidx = ((c >> 3) << 2) | ((c >> 1) & 3);
        bool hi = c & 1;
        float S = 0.f, S2 = 0.f;
#pragma unroll 8
        for (int ii = 0; ii < 32; ii++) {
            float lo, h2;
            unpack2(red_u[ii * 32 + uidx], lo, h2);      S  += hi ? h2 : lo;
            unpack2(red_u[ii * 32 + 16 + uidx], lo, h2); S2 += hi ? h2 : lo;
        }
        float mean = S * (1.0f / 1024.0f);
        float var  = S2 * (1.0f / 1024.0f) - mean * mean;
        float al = gamma2[c] * rsqrtf(var + 1e-5f);
        bn2[c] = al;
        bn2[32 + c] = beta2[c] - al * mean;
    }
    __syncthreads();

    // ---- BN2 apply + relu + max over j (relu commutes with max; init 0) ----
    float mxv[4][2];
#pragma unroll
    for (int cp = 0; cp < 4; cp++) {
        int c0 = ch * 8 + 2 * cp;
        float a0 = bn2[c0], a1 = bn2[c0 + 1];
        float b0 = bn2[32 + c0], b1v = bn2[33 + c0];
        float m0 = 0.f, m1 = 0.f;
#pragma unroll
        for (int jj = 0; jj < 4; jj++) {
            float y0, y1; unpack2(acc2[jj][cp], y0, y1);
            m0 = fmaxf(m0, a0 * y0 + b0);
            m1 = fmaxf(m1, a1 * y1 + b1v);
        }
#pragma unroll
        for (int d = 4; d <= 16; d <<= 1) {
            m0 = fmaxf(m0, __shfl_xor_sync(0xffffffffu, m0, d));
            m1 = fmaxf(m1, __shfl_xor_sync(0xffffffffu, m1, d));
        }
        mxv[cp][0] = m0; mxv[cp][1] = m1;
    }
    if (j4 == 0) {
        float4* op = (float4*)(out + (size_t)(base + i) * 32 + ch * 8);
        op[0] = make_float4(mxv[0][0], mxv[0][1], mxv[1][0], mxv[1][1]);
        op[1] = make_float4(mxv[2][0], mxv[2][1], mxv[3][0], mxv[3][1]);
    }
}

extern "C" void kernel_launch(void* const* d_in, const int* in_sizes, int n_in,
                              void* d_out, int out_size) {
    const float* h_states = (const float*)d_in[0];
    // d_in[1] = seq_start_end (uniform groups of 32; structure implied by shapes)
    const float* end_pos  = (const float*)d_in[2];
    const float* Wsp      = (const float*)d_in[3];
    const float* bsp      = (const float*)d_in[4];
    const float* W1       = (const float*)d_in[5];
    const float* b1       = (const float*)d_in[6];
    const float* gamma1   = (const float*)d_in[7];
    const float* beta1    = (const float*)d_in[8];
    const float* W2       = (const float*)d_in[9];
    const float* b2       = (const float*)d_in[10];
    const float* gamma2   = (const float*)d_in[11];
    const float* beta2    = (const float*)d_in[12];
    float* out = (float*)d_out;

    cudaFuncSetAttribute(pool_kernel, cudaFuncAttributeMaxDynamicSharedMemorySize, SMEM_BYTES);

    prep_kernel<<<1, 512>>>(Wsp, bsp, W1, b1);
    pool_kernel<<<256, 1024, SMEM_BYTES>>>(h_states, end_pos, W1, gamma1, beta1,
                                           W2, b2, gamma2, beta2, out);
}

// round 7
// speedup vs baseline: 2.1371x; 1.1365x over previous
#include <cuda_runtime.h>

typedef unsigned long long ull;

#define GSZ 32
#define ATS 36   // aT row stride (floats): float4-aligned rows, XOR-swizzled blocks
#define AT4S 9   // aT row stride in float4
#define UTS 33   // uT row stride (floats)

// smem layout (floats): aT[512*36] | uT[512*33] | W2s[512*32] | hs[32*68] | red[2048] | bn2[64]
#define OFF_AT   0
#define OFF_UT   (512*ATS)
#define OFF_W2   (OFF_UT + 512*UTS)
#define OFF_HS   (OFF_W2 + 512*32)
#define OFF_RED  (OFF_HS + 32*68)
#define OFF_BN2  (OFF_RED + 2048)
#define SMEM_FLOATS (OFF_BN2 + 64)
#define SMEM_BYTES  (SMEM_FLOATS * 4)

__device__ float g_M0[512];
__device__ float g_M1[512];
__device__ float g_cv[512];

__device__ __forceinline__ ull pack2(float lo, float hi) {
    ull r; asm("mov.b64 %0, {%1,%2};" : "=l"(r) : "f"(lo), "f"(hi)); return r;
}
__device__ __forceinline__ void unpack2(ull v, float& lo, float& hi) {
    asm("mov.b64 {%0,%1}, %2;" : "=f"(lo), "=f"(hi) : "l"(v));
}
__device__ __forceinline__ ull ffma2(ull a, ull b, ull c) {
    ull d; asm("fma.rn.f32x2 %0, %1, %2, %3;" : "=l"(d) : "l"(a), "l"(b), "l"(c)); return d;
}
__device__ __forceinline__ ull fadd2(ull a, ull b) {
    ull d; asm("add.rn.f32x2 %0, %1, %2;" : "=l"(d) : "l"(a), "l"(b)); return d;
}

// Fold W_spatial through W1's top half:  M = Wsp @ W1[:64],  cv = bsp @ W1[:64] + b1
__global__ void prep_kernel(const float* __restrict__ Wsp, const float* __restrict__ bsp,
                            const float* __restrict__ W1, const float* __restrict__ b1) {
    int k = threadIdx.x;  // 512 threads
    float m0 = 0.f, m1 = 0.f, cc = 0.f;
#pragma unroll 8
    for (int e = 0; e < 64; e++) {
        float w = W1[e * 512 + k];
        m0 += Wsp[e] * w;
        m1 += Wsp[64 + e] * w;
        cc += bsp[e] * w;
    }
    g_M0[k] = m0; g_M1[k] = m1; g_cv[k] = cc + b1[k];
}

__global__ void __launch_bounds__(1024, 1)
pool_kernel(const float* __restrict__ h_states, const float* __restrict__ end_pos,
            const float* __restrict__ W1,
            const float* __restrict__ gamma1, const float* __restrict__ beta1,
            const float* __restrict__ W2, const float* __restrict__ b2,
            const float* __restrict__ gamma2, const float* __restrict__ beta2,
            float* __restrict__ out) {
    extern __shared__ float sm[];
    float* aT  = sm + OFF_AT;
    float* uT  = sm + OFF_UT;
    float* W2s = sm + OFF_W2;
    float* hs  = sm + OFF_HS;
    float* red = sm + OFF_RED;
    float* bn2 = sm + OFF_BN2;

    const int n    = blockIdx.x;
    const int tid  = threadIdx.x;
    const int base = n * GSZ;

    // ---- cooperative loads: W2 -> smem, h rows -> smem (padded stride 68) ----
    {
        const float4* src = (const float4*)W2;
        float4* dst = (float4*)W2s;
        for (int idx = tid; idx < 512 * 32 / 4; idx += 1024) dst[idx] = src[idx];
        for (int idx = tid; idx < 32 * 64; idx += 1024) {
            int jr = idx >> 6, t = idx & 63;
            hs[jr * 68 + t] = h_states[(size_t)(base + jr) * 64 + t];
        }
    }
    __syncthreads();

    // ---- phase 1: a_j[k] = hW[j,k] + u_j[k] + cv[k];  u stored separately ----
    // thread = (j = tid>>5, q = tid&31): 16 k-values (q*16 .. q*16+15) for ped j
    {
        const int j  = tid >> 5;
        const int q  = tid & 31;
        const int k0 = q * 16;
        const float2 p = ((const float2*)end_pos)[base + j];
        const float px = p.x, py = p.y;
        const float* hrow = hs + j * 68;

        ull acc[8];
#pragma unroll
        for (int t = 0; t < 8; t++) acc[t] = 0ull;
        const float* wb = W1 + 64 * 512 + k0;
#pragma unroll 2
        for (int t = 0; t < 64; t++) {
            float hv = hrow[t];
            ull hh = pack2(hv, hv);
            const ulonglong2* wp = (const ulonglong2*)(wb + (size_t)t * 512);
            ulonglong2 wa = wp[0], wbv = wp[1], wc = wp[2], wd = wp[3];
            acc[0] = ffma2(hh, wa.x,  acc[0]); acc[1] = ffma2(hh, wa.y,  acc[1]);
            acc[2] = ffma2(hh, wbv.x, acc[2]); acc[3] = ffma2(hh, wbv.y, acc[3]);
            acc[4] = ffma2(hh, wc.x,  acc[4]); acc[5] = ffma2(hh, wc.y,  acc[5]);
            acc[6] = ffma2(hh, wd.x,  acc[6]); acc[7] = ffma2(hh, wd.y,  acc[7]);
        }
#pragma unroll
        for (int qq = 0; qq < 8; qq++) {
            int k = k0 + 2 * qq;
            float lo, hi; unpack2(acc[qq], lo, hi);
            float2 m0 = *(const float2*)(g_M0 + k);
            float2 m1 = *(const float2*)(g_M1 + k);
            float2 cv = *(const float2*)(g_cv + k);
            float u0 = px * m0.x + py * m1.x;
            float u1 = px * m0.y + py * m1.y;
            // XOR swizzle: physical j' = j ^ (((k>>4)&7)<<2); k,k+1 share (k>>4)
            int jA = j ^ (((k >> 4) & 7) << 2);
            aT[(k    ) * ATS + jA] = lo + u0 + cv.x;
            aT[(k + 1) * ATS + jA] = hi + u1 + cv.y;
            uT[(k    ) * UTS + jA] = u0;
            uT[(k + 1) * UTS + jA] = u1;
        }
    }
    __syncthreads();

    // ---- phase 2: BN1 via factored statistics (order-free over swizzled j) ----
    // 2 threads per feature: thread handles 16 physical j's, combine via shfl.
    {
        const int k  = tid >> 1;
        const int jo = (tid & 1) * 16;
        float sa = 0.f, sa2 = 0.f, su = 0.f, su2 = 0.f;
#pragma unroll 4
        for (int jj = 0; jj < 16; jj++) {
            float a = aT[k * ATS + jo + jj]; sa += a; sa2 += a * a;
            float u = uT[k * UTS + jo + jj]; su += u; su2 += u * u;
        }
        sa  += __shfl_xor_sync(0xffffffffu, sa,  1);
        sa2 += __shfl_xor_sync(0xffffffffu, sa2, 1);
        su  += __shfl_xor_sync(0xffffffffu, su,  1);
        su2 += __shfl_xor_sync(0xffffffffu, su2, 1);
        const float inv = 1.0f / 32.0f;
        float ma = sa * inv, mu = su * inv;
        float var  = (sa2 * inv - ma * ma) + (su2 * inv - mu * mu);
        float mean = ma - mu;
        float al = gamma1[k] * rsqrtf(var + 1e-5f);
        float bp = beta1[k] - al * mean;
#pragma unroll 4
        for (int jj = 0; jj < 16; jj++) {
            aT[k * ATS + jo + jj] = al * aT[k * ATS + jo + jj] + bp;   // a-tilde
            uT[k * UTS + jo + jj] = al * uT[k * UTS + jo + jj];        // u-tilde
        }
    }
    __syncthreads();

    // ---- phase 3: layer-2 GEMM.  relu(aT'[k][j] - uT'[k][i]) @ W2  (f32x2) ----
    // thread = (i = tid>>5, j4 = (tid>>2)&7, ch = tid&3):
    //   rows j = j4*4..j4*4+3, cols ch*8..ch*8+7.  acc[4 rows][4 col-pairs].
    // k-loop split: outer 32 blocks of 16 (swizzle s const per block, all inner
    // LDS addresses become immediate offsets; full unroll for load batching).
    const int i  = tid >> 5;
    const int j4 = (tid >> 2) & 7;
    const int ch = tid & 3;
    ull acc2[4][4];
    {
        const ull* b2u = (const ull*)b2;
#pragma unroll
        for (int cp = 0; cp < 4; cp++) {
            ull b = b2u[ch * 4 + cp];
            acc2[0][cp] = b; acc2[1][cp] = b; acc2[2][cp] = b; acc2[3][cp] = b;
        }
    }
#pragma unroll 1
    for (int k16 = 0; k16 < 32; k16++) {
        const int s = k16 & 7;
        const float*  up = uT + k16 * (16 * UTS) + (i ^ (s << 2));
        const float4* ap = (const float4*)aT + k16 * (16 * AT4S) + (j4 ^ s);
        const ulonglong2* wp = (const ulonglong2*)W2s + k16 * (16 * 8) + ch * 2;
#pragma unroll
        for (int kk = 0; kk < 16; kk++) {
            float  u  = up[kk * UTS];          // uniform per warp (broadcast)
            float4 av = ap[kk * AT4S];         // conflict-free permutation
            ulonglong2 wA = wp[kk * 8], wB = wp[kk * 8 + 1];
            float x0 = fmaxf(av.x - u, 0.f);
            float x1 = fmaxf(av.y - u, 0.f);
            float x2 = fmaxf(av.z - u, 0.f);
            float x3 = fmaxf(av.w - u, 0.f);
            ull X0 = pack2(x0, x0), X1 = pack2(x1, x1);
            ull X2 = pack2(x2, x2), X3 = pack2(x3, x3);
            acc2[0][0] = ffma2(X0, wA.x, acc2[0][0]);
            acc2[1][0] = ffma2(X1, wA.x, acc2[1][0]);
            acc2[2][0] = ffma2(X2, wA.x, acc2[2][0]);
            acc2[3][0] = ffma2(X3, wA.x, acc2[3][0]);
            acc2[0][1] = ffma2(X0, wA.y, acc2[0][1]);
            acc2[1][1] = ffma2(X1, wA.y, acc2[1][1]);
            acc2[2][1] = ffma2(X2, wA.y, acc2[2][1]);
            acc2[3][1] = ffma2(X3, wA.y, acc2[3][1]);
            acc2[0][2] = ffma2(X0, wB.x, acc2[0][2]);
            acc2[1][2] = ffma2(X1, wB.x, acc2[1][2]);
            acc2[2][2] = ffma2(X2, wB.x, acc2[2][2]);
            acc2[3][2] = ffma2(X3, wB.x, acc2[3][2]);
            acc2[0][3] = ffma2(X0, wB.y, acc2[0][3]);
            acc2[1][3] = ffma2(X1, wB.y, acc2[1][3]);
            acc2[2][3] = ffma2(X2, wB.y, acc2[2][3]);
            acc2[3][3] = ffma2(X3, wB.y, acc2[3][3]);
        }
    }

    // ---- BN2 statistics: reduce over in-thread j then over j4 lanes ----
    {
        ull* red_u = (ull*)red;
#pragma unroll
        for (int cp = 0; cp < 4; cp++) {
            ull v0 = acc2[0][cp], v1 = acc2[1][cp], v2 = acc2[2][cp], v3 = acc2[3][cp];
            ull s = fadd2(fadd2(v0, v1), fadd2(v2, v3));
            ull qv = ffma2(v0, v0, ffma2(v1, v1, ffma2(v2, v2, ffma2(v3, v3, 0ull))));
#pragma unroll
            for (int d = 4; d <= 16; d <<= 1) {
                s  = fadd2(s,  __shfl_xor_sync(0xffffffffu, s,  d));
                qv = fadd2(qv, __shfl_xor_sync(0xffffffffu, qv, d));
            }
            if (j4 == 0) {
                red_u[i * 32 + ch * 4 + cp]      = s;
                red_u[i * 32 + 16 + ch * 4 + cp] = qv;
            }
        }
    }
    __syncthreads();
    if (tid < 32) {
        const ull* red_u = (const ull*)red;
        int c = tid;
        int uidx = ((c >> 3) << 2) | ((c >> 1) & 3);
        bool hi = c & 1;
        float S = 0.f, S2 = 0.f;
#pragma unroll 8
        for (int ii = 0; ii < 32; ii++) {
            float lo, h2;
            unpack2(red_u[ii * 32 + uidx], lo, h2);      S  += hi ? h2 : lo;
            unpack2(red_u[ii * 32 + 16 + uidx], lo, h2); S2 += hi ? h2 : lo;
        }
        float mean = S * (1.0f / 1024.0f);
        float var  = S2 * (1.0f / 1024.0f) - mean * mean;
        float al = gamma2[c] * rsqrtf(var + 1e-5f);
        bn2[c] = al;
        bn2[32 + c] = beta2[c] - al * mean;
    }
    __syncthreads();

    // ---- BN2 apply + relu + max over j (relu commutes with max; init 0) ----
    float mxv[4][2];
#pragma unroll
    for (int cp = 0; cp < 4; cp++) {
        int c0 = ch * 8 + 2 * cp;
        float a0 = bn2[c0], a1 = bn2[c0 + 1];
        float b0 = bn2[32 + c0], b1v = bn2[33 + c0];
        float m0 = 0.f, m1 = 0.f;
#pragma unroll
        for (int jj = 0; jj < 4; jj++) {
            float y0, y1; unpack2(acc2[jj][cp], y0, y1);
            m0 = fmaxf(m0, a0 * y0 + b0);
            m1 = fmaxf(m1, a1 * y1 + b1v);
        }
#pragma unroll
        for (int d = 4; d <= 16; d <<= 1) {
            m0 = fmaxf(m0, __shfl_xor_sync(0xffffffffu, m0, d));
            m1 = fmaxf(m1, __shfl_xor_sync(0xffffffffu, m1, d));
        }
        mxv[cp][0] = m0; mxv[cp][1] = m1;
    }
    if (j4 == 0) {
        float4* op = (float4*)(out + (size_t)(base + i) * 32 + ch * 8);
        op[0] = make_float4(mxv[0][0], mxv[0][1], mxv[1][0], mxv[1][1]);
        op[1] = make_float4(mxv[2][0], mxv[2][1], mxv[3][0], mxv[3][1]);
    }
}

extern "C" void kernel_launch(void* const* d_in, const int* in_sizes, int n_in,
                              void* d_out, int out_size) {
    const float* h_states = (const float*)d_in[0];
    // d_in[1] = seq_start_end (uniform groups of 32; structure implied by shapes)
    const float* end_pos  = (const float*)d_in[2];
    const float* Wsp      = (const float*)d_in[3];
    const float* bsp      = (const float*)d_in[4];
    const float* W1       = (const float*)d_in[5];
    const float* b1       = (const float*)d_in[6];
    const float* gamma1   = (const float*)d_in[7];
    const float* beta1    = (const float*)d_in[8];
    const float* W2       = (const float*)d_in[9];
    const float* b2       = (const float*)d_in[10];
    const float* gamma2   = (const float*)d_in[11];
    const float* beta2    = (const float*)d_in[12];
    float* out = (float*)d_out;

    cudaFuncSetAttribute(pool_kernel, cudaFuncAttributeMaxDynamicSharedMemorySize, SMEM_BYTES);

    prep_kernel<<<1, 512>>>(Wsp, bsp, W1, b1);
    pool_kernel<<<256, 1024, SMEM_BYTES>>>(h_states, end_pos, W1, gamma1, beta1,
                                           W2, b2, gamma2, beta2, out);
}